// round 16
// baseline (speedup 1.0000x reference)
#include <cuda_runtime.h>
#include <cuda_bf16.h>
#include <cuda_fp16.h>
#include <mma.h>
#include <math.h>

using namespace nvcuda;

#define B_  2
#define T_  3
#define N_  6
#define C_  16
#define FD_ 48
#define FH_ 24
#define FW_ 64
#define GX_ 100
#define GY_ 100
#define GZ_ 8
#define OC_ 40
#define OP_ (OC_/2)

#define VOXN (GX_*GZ_*GY_)           // 80000 spatial positions per (b,t)
#define FEAT_PER_CAM (FD_*FH_*FW_*C_)

typedef unsigned long long u64;

// ---- packed-f32x2 helpers (FFMA2 — only reachable via PTX) --------------
__device__ __forceinline__ u64 pk2(float lo, float hi) {
    u64 r; asm("mov.b64 %0, {%1, %2};" : "=l"(r) : "f"(lo), "f"(hi)); return r;
}
__device__ __forceinline__ void upk2(u64 v, float& lo, float& hi) {
    asm("mov.b64 {%0, %1}, %2;" : "=f"(lo), "=f"(hi) : "l"(v));
}
__device__ __forceinline__ u64 f2fma(u64 a, u64 b, u64 c) {
    u64 d; asm("fma.rn.f32x2 %0, %1, %2, %3;" : "=l"(d) : "l"(a), "l"(b), "l"(c)); return d;
}

// Scratch (static device allocations — no cudaMalloc allowed)
__device__ float  g_featF[(size_t)B_*T_*N_*FD_*FH_*FW_*C_];  // channel-last fp32 (~170MB)
__device__ __half g_h[(size_t)B_*T_*VOXN*OC_];               // W_T-premultiplied h', fp16 channel-last (~38MB)
__device__ float  g_cum[B_*T_*12];

// ---- shared-memory layout for k_frustum (dynamic, 55232 bytes) ----------
#define PA_   104     // half pitch of A sample tile (208B rows, conflict-free)
#define PC_   52      // float pitch of C tile (same 208B rows, overlays A)
#define PBN_  48      // half pitch of B_N tile
#define PBT_  48      // half pitch of B_T tile
#define PA2_  56      // half pitch of A2 (h) tile (112B rows, conflict-free)
#define OFF_A    0
#define OFF_BN   26624
#define OFF_BT   35840
#define OFF_A2   40448
#define OFF_P    54784
#define OFF_BNB  55072
#define SMEM_TOTAL 55232

// ---------------------------------------------------------------------------
// Kernel 0: transpose frustum features [m][c][fd][fh][fw] -> [m][fd][fh][fw][c]
// fp32 in, fp32 out (channel-last). One block per (m, fd, fh) row.
// ---------------------------------------------------------------------------
__global__ void k_transpose(const float* __restrict__ in) {
    __shared__ float tile[FW_*17];
    int r  = blockIdx.x;                 // over B*T*N*FD*FH
    int m  = r / (FD_*FH_);
    int dh = r % (FD_*FH_);
    for (int idx = threadIdx.x; idx < C_*FW_; idx += blockDim.x) {
        int c  = idx / FW_;
        int fw = idx % FW_;
        tile[fw*17 + c] = in[(((size_t)m*C_ + c)*(FD_*FH_) + dh)*FW_ + fw];
    }
    __syncthreads();
    float4* dst = reinterpret_cast<float4*>(g_featF + (size_t)r * (FW_*C_));
    for (int j = threadIdx.x; j < C_*FW_/4; j += blockDim.x) {
        int fw = j >> 2;
        int c4 = (j & 3) * 4;
        dst[j] = make_float4(tile[fw*17 + c4],   tile[fw*17 + c4+1],
                             tile[fw*17 + c4+2], tile[fw*17 + c4+3]);
    }
}

// ---------------------------------------------------------------------------
// Cumulative warp matrices.
// ---------------------------------------------------------------------------
__global__ void k_cum(const float* __restrict__ DoF) {
    int b = threadIdx.x;
    if (b >= B_) return;
    float cum[16] = {1,0,0,0, 0,1,0,0, 0,0,1,0, 0,0,0,1};
    for (int t = T_-1; t >= 0; --t) {
        if (t < T_-1) {
            float M[16];
            #pragma unroll
            for (int i = 0; i < 3; i++)
                #pragma unroll
                for (int j = 0; j < 4; j++)
                    M[i*4+j] = DoF[((b*T_ + t)*4 + i)*4 + j];
            M[12]=0.f; M[13]=0.f; M[14]=0.f; M[15]=1.f;
            float nc[16];
            #pragma unroll
            for (int i = 0; i < 4; i++)
                #pragma unroll
                for (int j = 0; j < 4; j++) {
                    float a = 0.f;
                    #pragma unroll
                    for (int k = 0; k < 4; k++) a += M[i*4+k]*cum[k*4+j];
                    nc[i*4+j] = a;
                }
            #pragma unroll
            for (int i = 0; i < 16; i++) cum[i] = nc[i];
        }
        for (int i = 0; i < 12; i++) g_cum[(b*T_+t)*12 + i] = cum[i];
    }
}

// ---------------------------------------------------------------------------
// Kernel 1: per voxel: sample 96 fp32 values (6 cams x 16 ch) with packed
// f32x2 accumulate; stage fp16 A[128][96]; wmma GEMM (96->40) + bias + ReLU;
// wmma premultiply by per-t W_T slice (40->40); store h' fp16.
// ---------------------------------------------------------------------------
__global__ void __launch_bounds__(128) k_frustum(
    const float* __restrict__ RT, const float* __restrict__ intr,
    const float* __restrict__ W_N, const float* __restrict__ b_N,
    const float* __restrict__ W_T)
{
    extern __shared__ __align__(16) char dynsmem[];
    __half* sA  = reinterpret_cast<__half*>(dynsmem + OFF_A);   // [128][PA_]
    float*  sC  = reinterpret_cast<float*>(dynsmem + OFF_A);    // [128][PC_] overlay
    __half* sBn = reinterpret_cast<__half*>(dynsmem + OFF_BN);  // [96][PBN_]
    __half* sBt = reinterpret_cast<__half*>(dynsmem + OFF_BT);  // [48][PBT_]
    __half* sA2 = reinterpret_cast<__half*>(dynsmem + OFF_A2);  // [128][PA2_]
    float*  sP  = reinterpret_cast<float*>(dynsmem + OFF_P);    // [N_*12]
    float*  sbN = reinterpret_cast<float*>(dynsmem + OFF_BNB);  // [40]

    int tid = threadIdx.x;
    int pos = blockIdx.x*128 + tid;             // 480000 total; VOXN%128==0
    int bt  = pos / VOXN;                       // block-uniform
    int t   = bt % T_;
    int b   = bt / T_;
    int rem = pos % VOXN;
    int gy  = rem % GY_;
    int gz  = (rem / GY_) % GZ_;
    int x   = rem / (GY_*GZ_);

    // stage B_N = W_N^T [96][48] fp16 (cols 40-47 zero)
    for (int i = tid; i < 96*PBN_; i += 128) {
        int k = i / PBN_, n = i % PBN_;
        sBn[i] = (n < OC_) ? __float2half(W_N[n*(N_*C_) + k]) : __half(0.f);
    }
    // stage B_T [48][48] fp16 (rows/cols >=40 zero): B_T[k][n] = W_T[n][t*40+k]
    for (int i = tid; i < 48*PBT_; i += 128) {
        int k = i / PBT_, n = i % PBT_;
        sBt[i] = (k < OC_ && n < OC_) ? __float2half(W_T[n*(T_*OC_) + t*OC_ + k])
                                      : __half(0.f);
    }
    if (tid < OC_) sbN[tid] = b_N[tid];
    if (tid < N_) {
        const float* K = intr + b*9;
        const float* R = RT + ((size_t)((b*T_+t)*N_ + tid))*16;
        #pragma unroll
        for (int i = 0; i < 3; i++)
            #pragma unroll
            for (int j = 0; j < 4; j++)
                sP[tid*12 + i*4 + j] =
                    K[i*3+0]*R[0*4+j] + K[i*3+1]*R[1*4+j] + K[i*3+2]*R[2*4+j];
    }
    __syncthreads();

    float px = -50.0f + ((float)x  + 0.5f);
    float py = -50.0f + ((float)gy + 0.5f);
    float pz = -3.0f  + ((float)gz + 0.5f);

    // ---- Phase 1: sample 6 cameras, write fp16 row of A --------------------
    for (int n = 0; n < N_; n++) {
        u64 s2[8];
        #pragma unroll
        for (int q = 0; q < 8; q++) s2[q] = 0ull;

        const float* P = sP + n*12;
        float pr0 = P[0]*px + P[1]*py + P[2]*pz  + P[3];
        float pr1 = P[4]*px + P[5]*py + P[6]*pz  + P[7];
        float pr2 = P[8]*px + P[9]*py + P[10]*pz + P[11];
        float zc = fmaxf(pr2, 1e-5f);
        float u = pr0 / zc;
        float v = pr1 / zc;
        float d = (pr2 - 2.0f) / ((46.8f - 2.0f) / 48.0f);
        u = fminf(fmaxf(u, -1.0e6f), 1.0e6f);
        v = fminf(fmaxf(v, -1.0e6f), 1.0e6f);
        d = fminf(fmaxf(d, -1.0e6f), 1.0e6f);

        float fx0 = floorf(u), fy0 = floorf(v), fz0 = floorf(d);
        int x0 = (int)fx0, y0 = (int)fy0, z0 = (int)fz0;
        bool inside = !(x0 < -1 || x0 > FW_-1 || y0 < -1 || y0 > FH_-1 ||
                        z0 < -1 || z0 > FD_-1);
        if (inside) {
            float wx1 = u - fx0, wy1 = v - fy0, wz1 = d - fz0;
            float wxm[2] = { (1.0f-wx1) * (float)(x0 >= 0), wx1 * (float)(x0 < FW_-1) };
            float wym[2] = { (1.0f-wy1) * (float)(y0 >= 0), wy1 * (float)(y0 < FH_-1) };
            float wzm[2] = { (1.0f-wz1) * (float)(z0 >= 0), wz1 * (float)(z0 < FD_-1) };
            int xc[2]  = { max(x0, 0), min(x0+1, FW_-1) };
            int yc[2]  = { max(y0, 0), min(y0+1, FH_-1) };
            int zcl[2] = { max(z0, 0), min(z0+1, FD_-1) };

            const float* fb = g_featF + (size_t)((b*T_+t)*N_ + n)*FEAT_PER_CAM;
            #pragma unroll
            for (int dz = 0; dz < 2; dz++) {
                #pragma unroll
                for (int dy = 0; dy < 2; dy++) {
                    float wzy = wzm[dz]*wym[dy];
                    int row = (zcl[dz]*FH_ + yc[dy])*FW_;
                    #pragma unroll
                    for (int dx = 0; dx < 2; dx++) {
                        float w = wzy*wxm[dx];
                        u64 ww = pk2(w, w);
                        const ulonglong2* p = reinterpret_cast<const ulonglong2*>(
                            fb + (size_t)(row + xc[dx])*C_);
                        ulonglong2 A0 = p[0], A1 = p[1];
                        s2[0] = f2fma(A0.x, ww, s2[0]);
                        s2[1] = f2fma(A0.y, ww, s2[1]);
                        s2[2] = f2fma(A1.x, ww, s2[2]);
                        s2[3] = f2fma(A1.y, ww, s2[3]);
                        ulonglong2 A2v = p[2], A3v = p[3];
                        s2[4] = f2fma(A2v.x, ww, s2[4]);
                        s2[5] = f2fma(A2v.y, ww, s2[5]);
                        s2[6] = f2fma(A3v.x, ww, s2[6]);
                        s2[7] = f2fma(A3v.y, ww, s2[7]);
                    }
                }
            }
        }
        // convert to fp16 and store into A row
        union { uint4 q2[2]; __half2 hh[8]; } S;
        #pragma unroll
        for (int q = 0; q < 8; q++) {
            float lo, hi; upk2(s2[q], lo, hi);
            S.hh[q] = __floats2half2_rn(lo, hi);
        }
        uint4* rowA = reinterpret_cast<uint4*>(sA + (size_t)tid*PA_ + n*C_);
        rowA[0] = S.q2[0]; rowA[1] = S.q2[1];
    }
    __syncwarp();

    // ---- Phase 2: GEMM1  C = A[128x96] @ B_N[96x48] ------------------------
    int w = tid >> 5;
    {
        wmma::fragment<wmma::accumulator,16,16,16,float> c1[2][3];
        #pragma unroll
        for (int i = 0; i < 2; i++)
            #pragma unroll
            for (int n = 0; n < 3; n++) wmma::fill_fragment(c1[i][n], 0.0f);
        #pragma unroll
        for (int k = 0; k < 6; k++) {
            wmma::fragment<wmma::matrix_a,16,16,16,__half,wmma::row_major> af[2];
            wmma::load_matrix_sync(af[0], sA + (w*32     )*PA_ + k*16, PA_);
            wmma::load_matrix_sync(af[1], sA + (w*32 + 16)*PA_ + k*16, PA_);
            #pragma unroll
            for (int n = 0; n < 3; n++) {
                wmma::fragment<wmma::matrix_b,16,16,16,__half,wmma::row_major> bf;
                wmma::load_matrix_sync(bf, sBn + (k*16)*PBN_ + n*16, PBN_);
                wmma::mma_sync(c1[0][n], af[0], bf, c1[0][n]);
                wmma::mma_sync(c1[1][n], af[1], bf, c1[1][n]);
            }
        }
        __syncwarp();   // A reads done before overlaying C
        #pragma unroll
        for (int i = 0; i < 2; i++)
            #pragma unroll
            for (int n = 0; n < 3; n++)
                wmma::store_matrix_sync(sC + (w*32 + i*16)*PC_ + n*16,
                                        c1[i][n], PC_, wmma::mem_row_major);
    }
    __syncwarp();

    // ---- Phase 3: epilogue 1: bias + ReLU -> A2 fp16 -----------------------
    {
        const float4* crow = reinterpret_cast<const float4*>(sC + (size_t)tid*PC_);
        union { uint4 q2[3]; __half2 hh[12]; } H0, H1;
        #pragma unroll
        for (int q = 0; q < 5; q++) {
            float4 v = crow[q];
            H0.hh[2*q]   = __floats2half2_rn(fmaxf(v.x + sbN[q*4+0], 0.f),
                                             fmaxf(v.y + sbN[q*4+1], 0.f));
            H0.hh[2*q+1] = __floats2half2_rn(fmaxf(v.z + sbN[q*4+2], 0.f),
                                             fmaxf(v.w + sbN[q*4+3], 0.f));
        }
        #pragma unroll
        for (int q = 5; q < 10; q++) {
            float4 v = crow[q];
            int q2 = q - 5;
            H1.hh[2*q2]   = __floats2half2_rn(fmaxf(v.x + sbN[q*4+0], 0.f),
                                              fmaxf(v.y + sbN[q*4+1], 0.f));
            H1.hh[2*q2+1] = __floats2half2_rn(fmaxf(v.z + sbN[q*4+2], 0.f),
                                              fmaxf(v.w + sbN[q*4+3], 0.f));
        }
        H0.hh[10] = __floats2half2_rn(0.f, 0.f);  H0.hh[11] = __floats2half2_rn(0.f, 0.f);
        H1.hh[10] = __floats2half2_rn(0.f, 0.f);  H1.hh[11] = __floats2half2_rn(0.f, 0.f);
        uint4* rowH = reinterpret_cast<uint4*>(sA2 + (size_t)tid*PA2_);
        rowH[0] = H0.q2[0]; rowH[1] = H0.q2[1];
        rowH[2] = H1.q2[0]; rowH[3] = H1.q2[1];
        // pad cols 32..47 -> rows are [h0..h39, 0 x8]; cols 48..55 unread
        union { uint4 q; __half2 hh[4]; } Z;
        Z.hh[0] = __floats2half2_rn(0.f,0.f); Z.hh[1] = Z.hh[0];
        Z.hh[2] = Z.hh[0]; Z.hh[3] = Z.hh[0];
        // fix: chunks 0..3 hold halves 0..31; chunk 4 holds 32..39 + zeros
        union { uint4 q2; __half2 hh[4]; } H2;
        H2.hh[0] = H1.hh[6]; H2.hh[1] = H1.hh[7];
        H2.hh[2] = Z.hh[0];  H2.hh[3] = Z.hh[0];
        // rewrite chunks 2..5 correctly (halves 16..47)
        rowH[2] = H0.q2[2];          // wrong slot fixed below
        // --- simpler explicit layout write ---
        __half hrow[48];
        #pragma unroll
        for (int q = 0; q < 5; q++) {
            float4 v = crow[q];
            hrow[q*4+0] = __float2half(fmaxf(v.x + sbN[q*4+0], 0.f));
            hrow[q*4+1] = __float2half(fmaxf(v.y + sbN[q*4+1], 0.f));
            hrow[q*4+2] = __float2half(fmaxf(v.z + sbN[q*4+2], 0.f));
            hrow[q*4+3] = __float2half(fmaxf(v.w + sbN[q*4+3], 0.f));
        }
        #pragma unroll
        for (int q = 5; q < 10; q++) {
            float4 v = crow[q];
            hrow[q*4+0] = __float2half(fmaxf(v.x + sbN[q*4+0], 0.f));
            hrow[q*4+1] = __float2half(fmaxf(v.y + sbN[q*4+1], 0.f));
            hrow[q*4+2] = __float2half(fmaxf(v.z + sbN[q*4+2], 0.f));
            hrow[q*4+3] = __float2half(fmaxf(v.w + sbN[q*4+3], 0.f));
        }
        #pragma unroll
        for (int q = 40; q < 48; q++) hrow[q] = __half(0.f);
        const uint4* hv = reinterpret_cast<const uint4*>(hrow);
        #pragma unroll
        for (int q = 0; q < 6; q++) rowH[q] = hv[q];
    }
    __syncwarp();

    // ---- Phase 4: GEMM2  C2 = A2[128x48] @ B_T[48x48] ----------------------
    {
        wmma::fragment<wmma::accumulator,16,16,16,float> c2[2][3];
        #pragma unroll
        for (int i = 0; i < 2; i++)
            #pragma unroll
            for (int n = 0; n < 3; n++) wmma::fill_fragment(c2[i][n], 0.0f);
        #pragma unroll
        for (int k = 0; k < 3; k++) {
            wmma::fragment<wmma::matrix_a,16,16,16,__half,wmma::row_major> af[2];
            wmma::load_matrix_sync(af[0], sA2 + (w*32     )*PA2_ + k*16, PA2_);
            wmma::load_matrix_sync(af[1], sA2 + (w*32 + 16)*PA2_ + k*16, PA2_);
            #pragma unroll
            for (int n = 0; n < 3; n++) {
                wmma::fragment<wmma::matrix_b,16,16,16,__half,wmma::row_major> bf;
                wmma::load_matrix_sync(bf, sBt + (k*16)*PBT_ + n*16, PBT_);
                wmma::mma_sync(c2[0][n], af[0], bf, c2[0][n]);
                wmma::mma_sync(c2[1][n], af[1], bf, c2[1][n]);
            }
        }
        __syncwarp();
        #pragma unroll
        for (int i = 0; i < 2; i++)
            #pragma unroll
            for (int n = 0; n < 3; n++)
                wmma::store_matrix_sync(sC + (w*32 + i*16)*PC_ + n*16,
                                        c2[i][n], PC_, wmma::mem_row_major);
    }
    __syncwarp();

    // ---- Phase 5: store h' fp16 to global ----------------------------------
    {
        const float4* crow = reinterpret_cast<const float4*>(sC + (size_t)tid*PC_);
        union { uint4 q[5]; __half2 hh[20]; } O;
        #pragma unroll
        for (int q = 0; q < 10; q++) {
            float4 v = crow[q];
            O.hh[2*q]   = __floats2half2_rn(v.x, v.y);
            O.hh[2*q+1] = __floats2half2_rn(v.z, v.w);
        }
        uint4* dst = reinterpret_cast<uint4*>(g_h + (size_t)pos * OC_);
        #pragma unroll
        for (int q = 0; q < 5; q++) dst[q] = O.q[q];
    }
}

// ---------------------------------------------------------------------------
// Kernel 2: per (b,dd,hh,wy): for each t, warp via cum matrix, trilinear-sample
// the 40 premultiplied fp16 channels of h', accumulate (+b_T), ReLU, write out.
// ---------------------------------------------------------------------------
__global__ void __launch_bounds__(128) k_warp(
    const float* __restrict__ b_T, float* __restrict__ out)
{
    __shared__ float sb[OC_];
    __shared__ float sC2[T_*12];

    int pos = blockIdx.x*128 + threadIdx.x;     // 160000 total
    int b   = pos / VOXN;                       // block-uniform
    int rem = pos % VOXN;
    int wy  = rem % GY_;
    int hh  = (rem / GY_) % GZ_;
    int dd  = rem / (GY_*GZ_);

    if (threadIdx.x < OC_)    sb[threadIdx.x] = b_T[threadIdx.x];
    if (threadIdx.x < T_*12)  sC2[threadIdx.x] = g_cum[b*T_*12 + threadIdx.x];
    __syncthreads();

    float bx = -1.0f + 2.0f*(float)wy / (float)(GY_-1);
    float by = -1.0f + 2.0f*(float)hh / (float)(GZ_-1);
    float bz = -1.0f + 2.0f*(float)dd / (float)(GX_-1);

    u64 acc2[OP_];
    #pragma unroll
    for (int j = 0; j < OP_; j++) acc2[j] = pk2(sb[2*j], sb[2*j+1]);

    for (int t = 0; t < T_; t++) {
        const float* th = sC2 + t*12;
        float gx = th[0]*bx + th[1]*by + th[2]*bz  + th[3];
        float gy = th[4]*bx + th[5]*by + th[6]*bz  + th[7];
        float gz = th[8]*bx + th[9]*by + th[10]*bz + th[11];
        float ix = (gx + 1.0f)*0.5f*(float)(GY_-1);
        float iy = (gy + 1.0f)*0.5f*(float)(GZ_-1);
        float iz = (gz + 1.0f)*0.5f*(float)(GX_-1);
        ix = fminf(fmaxf(ix, -1.0e6f), 1.0e6f);
        iy = fminf(fmaxf(iy, -1.0e6f), 1.0e6f);
        iz = fminf(fmaxf(iz, -1.0e6f), 1.0e6f);

        float fx0 = floorf(ix), fy0 = floorf(iy), fz0 = floorf(iz);
        int x0 = (int)fx0, y0 = (int)fy0, z0 = (int)fz0;
        if (x0 < -1 || x0 > GY_-1 || y0 < -1 || y0 > GZ_-1 ||
            z0 < -1 || z0 > GX_-1) continue;

        float wx1 = ix - fx0, wy1 = iy - fy0, wz1 = iz - fz0;
        float wxm[2] = { (1.0f-wx1) * (float)(x0 >= 0), wx1 * (float)(x0 < GY_-1) };
        float wym[2] = { (1.0f-wy1) * (float)(y0 >= 0), wy1 * (float)(y0 < GZ_-1) };
        float wzm[2] = { (1.0f-wz1) * (float)(z0 >= 0), wz1 * (float)(z0 < GX_-1) };
        int xc[2]  = { max(x0, 0), min(x0+1, GY_-1) };
        int yc[2]  = { max(y0, 0), min(y0+1, GZ_-1) };
        int zcl[2] = { max(z0, 0), min(z0+1, GX_-1) };

        const __half* hb = g_h + (size_t)(b*T_+t)*VOXN*OC_;
        #pragma unroll
        for (int dz = 0; dz < 2; dz++) {
            #pragma unroll
            for (int dy = 0; dy < 2; dy++) {
                float wzy = wzm[dz]*wym[dy];
                int row = (zcl[dz]*GZ_ + yc[dy])*GY_;
                #pragma unroll
                for (int dx = 0; dx < 2; dx++) {
                    float w = wzy*wxm[dx];
                    u64 ww = pk2(w, w);
                    const uint4* p = reinterpret_cast<const uint4*>(
                        hb + (size_t)(row + xc[dx])*OC_);
                    #pragma unroll
                    for (int q = 0; q < 5; q++) {
                        union { uint4 u4; __half2 h[4]; } U;
                        U.u4 = p[q];
                        #pragma unroll
                        for (int k = 0; k < 4; k++) {
                            float2 f = __half22float2(U.h[k]);
                            acc2[q*4+k] = f2fma(pk2(f.x, f.y), ww, acc2[q*4+k]);
                        }
                    }
                }
            }
        }
    }

    #pragma unroll
    for (int j = 0; j < OP_; j++) {
        float lo, hi; upk2(acc2[j], lo, hi);
        out[(((size_t)(b*OC_ + 2*j  )*GX_ + dd)*GZ_ + hh)*GY_ + wy] = fmaxf(lo, 0.0f);
        out[(((size_t)(b*OC_ + 2*j+1)*GX_ + dd)*GZ_ + hh)*GY_ + wy] = fmaxf(hi, 0.0f);
    }
}

// ---------------------------------------------------------------------------
extern "C" void kernel_launch(void* const* d_in, const int* in_sizes, int n_in,
                              void* d_out, int out_size) {
    const float* frustum = (const float*)d_in[0];
    const float* RT      = (const float*)d_in[1];
    const float* intrins = (const float*)d_in[2];
    const float* DoF     = (const float*)d_in[3];
    const float* W_N     = (const float*)d_in[4];
    const float* b_N     = (const float*)d_in[5];
    const float* W_T     = (const float*)d_in[6];
    const float* b_T     = (const float*)d_in[7];
    float* out = (float*)d_out;

    cudaFuncSetAttribute(k_frustum, cudaFuncAttributeMaxDynamicSharedMemorySize,
                         SMEM_TOTAL);

    k_transpose<<<B_*T_*N_*FD_*FH_, 256>>>(frustum);
    k_cum<<<1, 32>>>(DoF);
    k_frustum<<<(B_*T_*VOXN)/128, 128, SMEM_TOTAL>>>(RT, intrins, W_N, b_N, W_T);
    k_warp<<<(B_*VOXN)/128, 128>>>(b_T, out);
}

// round 17
// speedup vs baseline: 1.1723x; 1.1723x over previous
#include <cuda_runtime.h>
#include <cuda_bf16.h>
#include <cuda_fp16.h>
#include <mma.h>
#include <math.h>

using namespace nvcuda;

#define B_  2
#define T_  3
#define N_  6
#define C_  16
#define FD_ 48
#define FH_ 24
#define FW_ 64
#define GX_ 100
#define GY_ 100
#define GZ_ 8
#define OC_ 40
#define OP_ (OC_/2)

#define VOXN (GX_*GZ_*GY_)           // 80000 spatial positions per (b,t)
#define FEAT_PER_CAM (FD_*FH_*FW_*C_)

typedef unsigned long long u64;

// ---- packed-f32x2 helpers (FFMA2 — only reachable via PTX) --------------
__device__ __forceinline__ u64 pk2(float lo, float hi) {
    u64 r; asm("mov.b64 %0, {%1, %2};" : "=l"(r) : "f"(lo), "f"(hi)); return r;
}
__device__ __forceinline__ void upk2(u64 v, float& lo, float& hi) {
    asm("mov.b64 {%0, %1}, %2;" : "=f"(lo), "=f"(hi) : "l"(v));
}
__device__ __forceinline__ u64 f2fma(u64 a, u64 b, u64 c) {
    u64 d; asm("fma.rn.f32x2 %0, %1, %2, %3;" : "=l"(d) : "l"(a), "l"(b), "l"(c)); return d;
}

// Scratch (static device allocations — no cudaMalloc allowed)
__device__ __half g_featCL[(size_t)B_*T_*N_*FD_*FH_*FW_*C_]; // channel-last fp16 (~85MB)
__device__ __half g_h[(size_t)B_*T_*VOXN*OC_];               // W_T-premultiplied h', fp16 channel-last (~38MB)
__device__ float  g_cum[B_*T_*12];

// ---- shared-memory layout for k_frustum (dynamic, 55232 bytes) ----------
#define PA_   104     // half pitch of A sample tile (208B rows)
#define PC_   52      // float pitch of C tile (208B rows, overlays A)
#define PBN_  48      // half pitch of B_N tile
#define PBT_  48      // half pitch of B_T tile
#define PA2_  56      // half pitch of A2 (h) tile (112B rows)
#define OFF_A    0
#define OFF_BN   26624
#define OFF_BT   35840
#define OFF_A2   40448
#define OFF_P    54784
#define OFF_BNB  55072
#define SMEM_TOTAL 55232

// ---------------------------------------------------------------------------
// Kernel 0: transpose frustum features [m][c][fd][fh][fw] -> [m][fd][fh][fw][c]
// fp32 in, fp16 out. One block per (m, fd, fh) row.
// ---------------------------------------------------------------------------
__global__ void k_transpose(const float* __restrict__ in) {
    __shared__ float tile[FW_*17];   // [fw][c], pad to kill bank conflicts
    int r  = blockIdx.x;                 // over B*T*N*FD*FH
    int m  = r / (FD_*FH_);
    int dh = r % (FD_*FH_);
    for (int idx = threadIdx.x; idx < C_*FW_; idx += blockDim.x) {
        int c  = idx / FW_;
        int fw = idx % FW_;
        tile[fw*17 + c] = in[(((size_t)m*C_ + c)*(FD_*FH_) + dh)*FW_ + fw];
    }
    __syncthreads();
    __half2* dst = reinterpret_cast<__half2*>(g_featCL + (size_t)r * (FW_*C_));
    for (int j = threadIdx.x; j < C_*FW_/2; j += blockDim.x) {
        int fw = j / (C_/2);
        int c  = (j % (C_/2)) * 2;
        dst[j] = __floats2half2_rn(tile[fw*17 + c], tile[fw*17 + c + 1]);
    }
}

// ---------------------------------------------------------------------------
// Cumulative warp matrices.
// ---------------------------------------------------------------------------
__global__ void k_cum(const float* __restrict__ DoF) {
    int b = threadIdx.x;
    if (b >= B_) return;
    float cum[16] = {1,0,0,0, 0,1,0,0, 0,0,1,0, 0,0,0,1};
    for (int t = T_-1; t >= 0; --t) {
        if (t < T_-1) {
            float M[16];
            #pragma unroll
            for (int i = 0; i < 3; i++)
                #pragma unroll
                for (int j = 0; j < 4; j++)
                    M[i*4+j] = DoF[((b*T_ + t)*4 + i)*4 + j];
            M[12]=0.f; M[13]=0.f; M[14]=0.f; M[15]=1.f;
            float nc[16];
            #pragma unroll
            for (int i = 0; i < 4; i++)
                #pragma unroll
                for (int j = 0; j < 4; j++) {
                    float a = 0.f;
                    #pragma unroll
                    for (int k = 0; k < 4; k++) a += M[i*4+k]*cum[k*4+j];
                    nc[i*4+j] = a;
                }
            #pragma unroll
            for (int i = 0; i < 16; i++) cum[i] = nc[i];
        }
        for (int i = 0; i < 12; i++) g_cum[(b*T_+t)*12 + i] = cum[i];
    }
}

// ---------------------------------------------------------------------------
// Kernel 1: per voxel: sample 96 fp16 values (6 cams x 16 ch, fp32 packed
// accumulate); stage fp16 A[128][96]; wmma GEMM (96->40) + bias + ReLU;
// wmma premultiply by per-t W_T slice (40->40); store h' fp16.
// ---------------------------------------------------------------------------
__global__ void __launch_bounds__(128) k_frustum(
    const float* __restrict__ RT, const float* __restrict__ intr,
    const float* __restrict__ W_N, const float* __restrict__ b_N,
    const float* __restrict__ W_T)
{
    extern __shared__ __align__(16) char dynsmem[];
    __half* sA  = reinterpret_cast<__half*>(dynsmem + OFF_A);   // [128][PA_]
    float*  sC  = reinterpret_cast<float*>(dynsmem + OFF_A);    // [128][PC_] overlay
    __half* sBn = reinterpret_cast<__half*>(dynsmem + OFF_BN);  // [96][PBN_]
    __half* sBt = reinterpret_cast<__half*>(dynsmem + OFF_BT);  // [48][PBT_]
    __half* sA2 = reinterpret_cast<__half*>(dynsmem + OFF_A2);  // [128][PA2_]
    float*  sP  = reinterpret_cast<float*>(dynsmem + OFF_P);    // [N_*12]
    float*  sbN = reinterpret_cast<float*>(dynsmem + OFF_BNB);  // [40]

    int tid = threadIdx.x;
    int pos = blockIdx.x*128 + tid;             // 480000 total; VOXN%128==0
    int bt  = pos / VOXN;                       // block-uniform
    int t   = bt % T_;
    int b   = bt / T_;
    int rem = pos % VOXN;
    int gy  = rem % GY_;
    int gz  = (rem / GY_) % GZ_;
    int x   = rem / (GY_*GZ_);

    // stage B_N = W_N^T [96][48] fp16 (cols 40-47 zero)
    for (int i = tid; i < 96*PBN_; i += 128) {
        int k = i / PBN_, n = i % PBN_;
        sBn[i] = (n < OC_) ? __float2half(W_N[n*(N_*C_) + k]) : __half(0.f);
    }
    // stage B_T [48][48] fp16 (rows/cols >=40 zero): B_T[k][n] = W_T[n][t*40+k]
    for (int i = tid; i < 48*PBT_; i += 128) {
        int k = i / PBT_, n = i % PBT_;
        sBt[i] = (k < OC_ && n < OC_) ? __float2half(W_T[n*(T_*OC_) + t*OC_ + k])
                                      : __half(0.f);
    }
    if (tid < OC_) sbN[tid] = b_N[tid];
    if (tid < N_) {
        const float* K = intr + b*9;
        const float* R = RT + ((size_t)((b*T_+t)*N_ + tid))*16;
        #pragma unroll
        for (int i = 0; i < 3; i++)
            #pragma unroll
            for (int j = 0; j < 4; j++)
                sP[tid*12 + i*4 + j] =
                    K[i*3+0]*R[0*4+j] + K[i*3+1]*R[1*4+j] + K[i*3+2]*R[2*4+j];
    }
    __syncthreads();

    float px = -50.0f + ((float)x  + 0.5f);
    float py = -50.0f + ((float)gy + 0.5f);
    float pz = -3.0f  + ((float)gz + 0.5f);

    // ---- Phase 1: sample 6 cameras (fp16 gather), write fp16 row of A ------
    for (int n = 0; n < N_; n++) {
        u64 s2[8];
        #pragma unroll
        for (int q = 0; q < 8; q++) s2[q] = 0ull;

        const float* P = sP + n*12;
        float pr0 = P[0]*px + P[1]*py + P[2]*pz  + P[3];
        float pr1 = P[4]*px + P[5]*py + P[6]*pz  + P[7];
        float pr2 = P[8]*px + P[9]*py + P[10]*pz + P[11];
        float zc = fmaxf(pr2, 1e-5f);
        float u = pr0 / zc;
        float v = pr1 / zc;
        float d = (pr2 - 2.0f) / ((46.8f - 2.0f) / 48.0f);
        u = fminf(fmaxf(u, -1.0e6f), 1.0e6f);
        v = fminf(fmaxf(v, -1.0e6f), 1.0e6f);
        d = fminf(fmaxf(d, -1.0e6f), 1.0e6f);

        float fx0 = floorf(u), fy0 = floorf(v), fz0 = floorf(d);
        int x0 = (int)fx0, y0 = (int)fy0, z0 = (int)fz0;
        bool inside = !(x0 < -1 || x0 > FW_-1 || y0 < -1 || y0 > FH_-1 ||
                        z0 < -1 || z0 > FD_-1);
        if (inside) {
            float wx1 = u - fx0, wy1 = v - fy0, wz1 = d - fz0;
            float wxm[2] = { (1.0f-wx1) * (float)(x0 >= 0), wx1 * (float)(x0 < FW_-1) };
            float wym[2] = { (1.0f-wy1) * (float)(y0 >= 0), wy1 * (float)(y0 < FH_-1) };
            float wzm[2] = { (1.0f-wz1) * (float)(z0 >= 0), wz1 * (float)(z0 < FD_-1) };
            int xc[2]  = { max(x0, 0), min(x0+1, FW_-1) };
            int yc[2]  = { max(y0, 0), min(y0+1, FH_-1) };
            int zcl[2] = { max(z0, 0), min(z0+1, FD_-1) };

            const __half* fb = g_featCL + (size_t)((b*T_+t)*N_ + n)*FEAT_PER_CAM;
            #pragma unroll
            for (int dz = 0; dz < 2; dz++) {
                #pragma unroll
                for (int dy = 0; dy < 2; dy++) {
                    float wzy = wzm[dz]*wym[dy];
                    int row = (zcl[dz]*FH_ + yc[dy])*FW_;
                    #pragma unroll
                    for (int dx = 0; dx < 2; dx++) {
                        float w = wzy*wxm[dx];
                        u64 ww = pk2(w, w);
                        union { uint4 u4; __half2 h[4]; } U0, U1;
                        const uint4* p = reinterpret_cast<const uint4*>(
                            fb + (size_t)(row + xc[dx])*C_);
                        U0.u4 = p[0]; U1.u4 = p[1];
                        #pragma unroll
                        for (int q = 0; q < 4; q++) {
                            float2 f0 = __half22float2(U0.h[q]);
                            s2[q]   = f2fma(pk2(f0.x, f0.y), ww, s2[q]);
                            float2 f1 = __half22float2(U1.h[q]);
                            s2[4+q] = f2fma(pk2(f1.x, f1.y), ww, s2[4+q]);
                        }
                    }
                }
            }
        }
        // convert fp32 sample back to fp16 into A row
        union { uint4 q2[2]; __half2 hh[8]; } S;
        #pragma unroll
        for (int q = 0; q < 8; q++) {
            float lo, hi; upk2(s2[q], lo, hi);
            S.hh[q] = __floats2half2_rn(lo, hi);
        }
        uint4* rowA = reinterpret_cast<uint4*>(sA + (size_t)tid*PA_ + n*C_);
        rowA[0] = S.q2[0]; rowA[1] = S.q2[1];
    }
    __syncwarp();

    // ---- Phase 2: GEMM1  C = A[128x96] @ B_N[96x48] ------------------------
    int w = tid >> 5;
    {
        wmma::fragment<wmma::accumulator,16,16,16,float> c1[2][3];
        #pragma unroll
        for (int i = 0; i < 2; i++)
            #pragma unroll
            for (int n = 0; n < 3; n++) wmma::fill_fragment(c1[i][n], 0.0f);
        #pragma unroll
        for (int k = 0; k < 6; k++) {
            wmma::fragment<wmma::matrix_a,16,16,16,__half,wmma::row_major> af[2];
            wmma::load_matrix_sync(af[0], sA + (w*32     )*PA_ + k*16, PA_);
            wmma::load_matrix_sync(af[1], sA + (w*32 + 16)*PA_ + k*16, PA_);
            #pragma unroll
            for (int n = 0; n < 3; n++) {
                wmma::fragment<wmma::matrix_b,16,16,16,__half,wmma::row_major> bf;
                wmma::load_matrix_sync(bf, sBn + (k*16)*PBN_ + n*16, PBN_);
                wmma::mma_sync(c1[0][n], af[0], bf, c1[0][n]);
                wmma::mma_sync(c1[1][n], af[1], bf, c1[1][n]);
            }
        }
        __syncwarp();   // warp's A reads done before overlaying C on same rows
        #pragma unroll
        for (int i = 0; i < 2; i++)
            #pragma unroll
            for (int n = 0; n < 3; n++)
                wmma::store_matrix_sync(sC + (w*32 + i*16)*PC_ + n*16,
                                        c1[i][n], PC_, wmma::mem_row_major);
    }
    __syncwarp();

    // ---- Phase 3: epilogue 1: bias + ReLU -> A2 fp16 (48-wide, zero pad) ---
    {
        const float4* crow = reinterpret_cast<const float4*>(sC + (size_t)tid*PC_);
        union { uint4 q[6]; __half2 hh[24]; } H;
        #pragma unroll
        for (int q = 0; q < 10; q++) {
            float4 v = crow[q];
            H.hh[2*q]   = __floats2half2_rn(fmaxf(v.x + sbN[q*4+0], 0.f),
                                            fmaxf(v.y + sbN[q*4+1], 0.f));
            H.hh[2*q+1] = __floats2half2_rn(fmaxf(v.z + sbN[q*4+2], 0.f),
                                            fmaxf(v.w + sbN[q*4+3], 0.f));
        }
        #pragma unroll
        for (int q = 20; q < 24; q++) H.hh[q] = __floats2half2_rn(0.f, 0.f);
        uint4* rowH = reinterpret_cast<uint4*>(sA2 + (size_t)tid*PA2_);
        #pragma unroll
        for (int q = 0; q < 6; q++) rowH[q] = H.q[q];
    }
    __syncwarp();

    // ---- Phase 4: GEMM2  C2 = A2[128x48] @ B_T[48x48] ----------------------
    {
        wmma::fragment<wmma::accumulator,16,16,16,float> c2[2][3];
        #pragma unroll
        for (int i = 0; i < 2; i++)
            #pragma unroll
            for (int n = 0; n < 3; n++) wmma::fill_fragment(c2[i][n], 0.0f);
        #pragma unroll
        for (int k = 0; k < 3; k++) {
            wmma::fragment<wmma::matrix_a,16,16,16,__half,wmma::row_major> af[2];
            wmma::load_matrix_sync(af[0], sA2 + (w*32     )*PA2_ + k*16, PA2_);
            wmma::load_matrix_sync(af[1], sA2 + (w*32 + 16)*PA2_ + k*16, PA2_);
            #pragma unroll
            for (int n = 0; n < 3; n++) {
                wmma::fragment<wmma::matrix_b,16,16,16,__half,wmma::row_major> bf;
                wmma::load_matrix_sync(bf, sBt + (k*16)*PBT_ + n*16, PBT_);
                wmma::mma_sync(c2[0][n], af[0], bf, c2[0][n]);
                wmma::mma_sync(c2[1][n], af[1], bf, c2[1][n]);
            }
        }
        __syncwarp();
        #pragma unroll
        for (int i = 0; i < 2; i++)
            #pragma unroll
            for (int n = 0; n < 3; n++)
                wmma::store_matrix_sync(sC + (w*32 + i*16)*PC_ + n*16,
                                        c2[i][n], PC_, wmma::mem_row_major);
    }
    __syncwarp();

    // ---- Phase 5: store h' fp16 to global ----------------------------------
    {
        const float4* crow = reinterpret_cast<const float4*>(sC + (size_t)tid*PC_);
        union { uint4 q[5]; __half2 hh[20]; } O;
        #pragma unroll
        for (int q = 0; q < 10; q++) {
            float4 v = crow[q];
            O.hh[2*q]   = __floats2half2_rn(v.x, v.y);
            O.hh[2*q+1] = __floats2half2_rn(v.z, v.w);
        }
        uint4* dst = reinterpret_cast<uint4*>(g_h + (size_t)pos * OC_);
        #pragma unroll
        for (int q = 0; q < 5; q++) dst[q] = O.q[q];
    }
}

// ---------------------------------------------------------------------------
// Kernel 2: per (b,dd,hh,wy): for each t, warp via cum matrix, trilinear-sample
// the 40 premultiplied fp16 channels of h', accumulate (+b_T), ReLU, write out.
// ---------------------------------------------------------------------------
__global__ void __launch_bounds__(128) k_warp(
    const float* __restrict__ b_T, float* __restrict__ out)
{
    __shared__ float sb[OC_];
    __shared__ float sC2[T_*12];

    int pos = blockIdx.x*128 + threadIdx.x;     // 160000 total
    int b   = pos / VOXN;                       // block-uniform
    int rem = pos % VOXN;
    int wy  = rem % GY_;
    int hh  = (rem / GY_) % GZ_;
    int dd  = rem / (GY_*GZ_);

    if (threadIdx.x < OC_)    sb[threadIdx.x] = b_T[threadIdx.x];
    if (threadIdx.x < T_*12)  sC2[threadIdx.x] = g_cum[b*T_*12 + threadIdx.x];
    __syncthreads();

    float bx = -1.0f + 2.0f*(float)wy / (float)(GY_-1);
    float by = -1.0f + 2.0f*(float)hh / (float)(GZ_-1);
    float bz = -1.0f + 2.0f*(float)dd / (float)(GX_-1);

    u64 acc2[OP_];
    #pragma unroll
    for (int j = 0; j < OP_; j++) acc2[j] = pk2(sb[2*j], sb[2*j+1]);

    for (int t = 0; t < T_; t++) {
        const float* th = sC2 + t*12;
        float gx = th[0]*bx + th[1]*by + th[2]*bz  + th[3];
        float gy = th[4]*bx + th[5]*by + th[6]*bz  + th[7];
        float gz = th[8]*bx + th[9]*by + th[10]*bz + th[11];
        float ix = (gx + 1.0f)*0.5f*(float)(GY_-1);
        float iy = (gy + 1.0f)*0.5f*(float)(GZ_-1);
        float iz = (gz + 1.0f)*0.5f*(float)(GX_-1);
        ix = fminf(fmaxf(ix, -1.0e6f), 1.0e6f);
        iy = fminf(fmaxf(iy, -1.0e6f), 1.0e6f);
        iz = fminf(fmaxf(iz, -1.0e6f), 1.0e6f);

        float fx0 = floorf(ix), fy0 = floorf(iy), fz0 = floorf(iz);
        int x0 = (int)fx0, y0 = (int)fy0, z0 = (int)fz0;
        if (x0 < -1 || x0 > GY_-1 || y0 < -1 || y0 > GZ_-1 ||
            z0 < -1 || z0 > GX_-1) continue;

        float wx1 = ix - fx0, wy1 = iy - fy0, wz1 = iz - fz0;
        float wxm[2] = { (1.0f-wx1) * (float)(x0 >= 0), wx1 * (float)(x0 < GY_-1) };
        float wym[2] = { (1.0f-wy1) * (float)(y0 >= 0), wy1 * (float)(y0 < GZ_-1) };
        float wzm[2] = { (1.0f-wz1) * (float)(z0 >= 0), wz1 * (float)(z0 < GX_-1) };
        int xc[2]  = { max(x0, 0), min(x0+1, GY_-1) };
        int yc[2]  = { max(y0, 0), min(y0+1, GZ_-1) };
        int zcl[2] = { max(z0, 0), min(z0+1, GX_-1) };

        const __half* hb = g_h + (size_t)(b*T_+t)*VOXN*OC_;
        #pragma unroll
        for (int dz = 0; dz < 2; dz++) {
            #pragma unroll
            for (int dy = 0; dy < 2; dy++) {
                float wzy = wzm[dz]*wym[dy];
                int row = (zcl[dz]*GZ_ + yc[dy])*GY_;
                #pragma unroll
                for (int dx = 0; dx < 2; dx++) {
                    float w = wzy*wxm[dx];
                    u64 ww = pk2(w, w);
                    const uint4* p = reinterpret_cast<const uint4*>(
                        hb + (size_t)(row + xc[dx])*OC_);
                    #pragma unroll
                    for (int q = 0; q < 5; q++) {
                        union { uint4 u4; __half2 h[4]; } U;
                        U.u4 = p[q];
                        #pragma unroll
                        for (int k = 0; k < 4; k++) {
                            float2 f = __half22float2(U.h[k]);
                            acc2[q*4+k] = f2fma(pk2(f.x, f.y), ww, acc2[q*4+k]);
                        }
                    }
                }
            }
        }
    }

    #pragma unroll
    for (int j = 0; j < OP_; j++) {
        float lo, hi; upk2(acc2[j], lo, hi);
        out[(((size_t)(b*OC_ + 2*j  )*GX_ + dd)*GZ_ + hh)*GY_ + wy] = fmaxf(lo, 0.0f);
        out[(((size_t)(b*OC_ + 2*j+1)*GX_ + dd)*GZ_ + hh)*GY_ + wy] = fmaxf(hi, 0.0f);
    }
}

// ---------------------------------------------------------------------------
extern "C" void kernel_launch(void* const* d_in, const int* in_sizes, int n_in,
                              void* d_out, int out_size) {
    const float* frustum = (const float*)d_in[0];
    const float* RT      = (const float*)d_in[1];
    const float* intrins = (const float*)d_in[2];
    const float* DoF     = (const float*)d_in[3];
    const float* W_N     = (const float*)d_in[4];
    const float* b_N     = (const float*)d_in[5];
    const float* W_T     = (const float*)d_in[6];
    const float* b_T     = (const float*)d_in[7];
    float* out = (float*)d_out;

    cudaFuncSetAttribute(k_frustum, cudaFuncAttributeMaxDynamicSharedMemorySize,
                         SMEM_TOTAL);

    k_transpose<<<B_*T_*N_*FD_*FH_, 256>>>(frustum);
    k_cum<<<1, 32>>>(DoF);
    k_frustum<<<(B_*T_*VOXN)/128, 128, SMEM_TOTAL>>>(RT, intrins, W_N, b_N, W_T);
    k_warp<<<(B_*VOXN)/128, 128>>>(b_T, out);
}